// round 17
// baseline (speedup 1.0000x reference)
#include <cuda_runtime.h>
#include <cuda_fp16.h>
#include <cuda_bf16.h>

// Problem constants
#define B    8
#define HIN  256
#define WIN  256
#define CV4  16      // C/4 channel chunks per pixel (C=64)
#define HP   64
#define WP   64

// 4 MB pooled averages in fp16 — static device scratch
__device__ uint2 g_pooled[B * HP * WP * CV4];

__device__ __forceinline__ void acc4(float4& a, const float4 v) {
    a.x += v.x; a.y += v.y; a.z += v.z; a.w += v.w;
}
__device__ __forceinline__ float4 blend2(float4 p, float wp, float4 q, float wq) {
    float4 r;
    r.x = p.x * wp + q.x * wq;
    r.y = p.y * wp + q.y * wq;
    r.z = p.z * wp + q.z * wq;
    r.w = p.w * wp + q.w * wq;
    return r;
}
__device__ __forceinline__ uint2 pack_h4(float4 v) {
    __half2 lo = __floats2half2_rn(v.x, v.y);
    __half2 hi = __floats2half2_rn(v.z, v.w);
    uint2 u;
    u.x = *reinterpret_cast<unsigned int*>(&lo);
    u.y = *reinterpret_cast<unsigned int*>(&hi);
    return u;
}
__device__ __forceinline__ float4 unpack_h4(uint2 u) {
    __half2 lo = *reinterpret_cast<__half2*>(&u.x);
    __half2 hi = *reinterpret_cast<__half2*>(&u.y);
    float2 a = __half22float2(lo);
    float2 b = __half22float2(hi);
    return make_float4(a.x, a.y, b.x, b.y);
}

// PDL primitives (validated under graph capture, R15/R16)
__device__ __forceinline__ void pdl_wait() {
    asm volatile("griddepcontrol.wait;" ::: "memory");
}
__device__ __forceinline__ void pdl_trigger() {
    asm volatile("griddepcontrol.launch_dependents;" ::: "memory");
}

__device__ __forceinline__ float4 colsum6(const float4* __restrict__ p, size_t RS) {
    float4 a0 = __ldg(p + 0 * RS);
    float4 a1 = __ldg(p + 1 * RS);
    float4 a2 = __ldg(p + 2 * RS);
    float4 a3 = __ldg(p + 3 * RS);
    float4 a4 = __ldg(p + 4 * RS);
    float4 a5 = __ldg(p + 5 * RS);
    float4 s;
    s.x = ((a0.x + a1.x) + (a2.x + a3.x)) + (a4.x + a5.x);
    s.y = ((a0.y + a1.y) + (a2.y + a3.y)) + (a4.y + a5.y);
    s.z = ((a0.z + a1.z) + (a2.z + a3.z)) + (a4.z + a5.z);
    s.w = ((a0.w + a1.w) + (a2.w + a3.w)) + (a4.w + a5.w);
    return s;
}
__device__ __forceinline__ float4 xor16_add(float4 e) {
    float4 t;
    t.x = e.x + __shfl_xor_sync(0xffffffffu, e.x, 16);
    t.y = e.y + __shfl_xor_sync(0xffffffffu, e.y, 16);
    t.z = e.z + __shfl_xor_sync(0xffffffffu, e.z, 16);
    t.w = e.w + __shfl_xor_sync(0xffffffffu, e.w, 16);
    return t;
}

// ---------------------------------------------------------------------------
// K1: SAME avg-pool 6x6 stride 4 — warp-synchronous, no smem, no barrier.
// One warp = pooled outputs (ox0, ox0+1). Lane (c4 = l&15, hl = l>>4) owns
// column sums for xl = hl + 2j, j=0..4 (global x = 4*ox0 - 1 + xl), i.e.
// every column loaded once per warp, each load 512 B warp-contiguous.
//   e0 = s0+s1+s2 (this parity's share of xl 0..5 -> output ox0)
//   e1 = s2+s3+s4 (share of xl 4..9 -> output ox0+1)
//   t = e + shfl_xor(e,16): full window sums on all lanes.
// Lanes 0-15 store ox0 (c4 = l), lanes 16-31 store ox0+1 (c4 = l-16).
// ---------------------------------------------------------------------------
__global__ __launch_bounds__(256) void pool_kernel(const float4* __restrict__ in4) {
    int gw   = (blockIdx.x * 256 + threadIdx.x) >> 5;   // 16384 warps
    int lane = threadIdx.x & 31;

    int ox0 = 2 * (gw & 31);
    int oy  = (gw >> 5) & 63;
    int b   = gw >> 11;

    int c4 = lane & 15;
    int hl = lane >> 4;
    int r0 = 4 * oy - 1;
    int xs = 4 * ox0 - 1 + hl;     // x of slot j is xs + 2j

    const float4* base = in4 + ((size_t)b * HIN * WIN) * CV4 + c4;
    const size_t RS = (size_t)WIN * CV4;

    float4 s[5];
    bool xint = (ox0 != 0) && (ox0 != 62);
    bool yint = (oy != 0) && (oy != 63);

    if (xint && yint) {
        const float4* p = base + ((size_t)r0 * WIN + xs) * CV4;
        #pragma unroll
        for (int j = 0; j < 5; ++j)
            s[j] = colsum6(p + (size_t)(2 * j) * CV4, RS);
    } else {
        #pragma unroll
        for (int j = 0; j < 5; ++j) {
            int x = xs + 2 * j;
            float4 a = make_float4(0.f, 0.f, 0.f, 0.f);
            if ((unsigned)x < 256u) {
                const float4* p = base + (size_t)x * CV4;
                #pragma unroll
                for (int r = 0; r < 6; ++r) {
                    int rr = r0 + r;
                    if ((unsigned)rr < 256u)
                        acc4(a, __ldg(p + (size_t)rr * RS));
                }
            }
            s[j] = a;
        }
    }

    float4 e0, e1;
    e0.x = s[0].x + s[1].x + s[2].x;  e0.y = s[0].y + s[1].y + s[2].y;
    e0.z = s[0].z + s[1].z + s[2].z;  e0.w = s[0].w + s[1].w + s[2].w;
    e1.x = s[2].x + s[3].x + s[4].x;  e1.y = s[2].y + s[3].y + s[4].y;
    e1.z = s[2].z + s[3].z + s[4].z;  e1.w = s[2].w + s[3].w + s[4].w;

    float4 t0 = xor16_add(e0);   // full sum, output ox0
    float4 t1 = xor16_add(e1);   // full sum, output ox0+1

    int ox = ox0 + hl;
    float4 tv = hl ? t1 : t0;

    int nr = 6 - (oy == 0) - (oy == 63);
    int nc = 6 - (ox == 0) - (ox == 63);
    float inv = 1.0f / (float)(nr * nc);
    g_pooled[(((size_t)b * HP + oy) * WP + ox) * CV4 + c4] =
        pack_h4(make_float4(tv.x * inv, tv.y * inv, tv.z * inv, tv.w * inv));

    pdl_trigger();
}

// ---------------------------------------------------------------------------
// K2: unaverage pool, direct streaming (proven 22.2-23.0us), fp16 taps,
// PDL consumer — byte-identical to R16.
// ---------------------------------------------------------------------------
__device__ __forceinline__ float d2s(float d) {
    if (d < 5.5f)   return (d - 2.0f) * (1.0f / 3.5f);
    if (d > 249.5f) return (d - 249.5f) * (1.0f / 3.5f) + 62.0f;
    return (d - 1.5f) * 0.25f;
}

__global__ __launch_bounds__(256, 6) void up_kernel(float4* __restrict__ out4) {
    int tid = blockIdx.x * 256 + threadIdx.x;   // B*256*32*16 = 1,048,576
    int c4 = tid & 15;
    int kk = (tid >> 4) & 31;
    int y  = (tid >> 9) & 255;
    int b  = tid >> 17;

    int k0 = kk * 2;

    float sr  = d2s((float)y);
    float r0f = floorf(sr);
    int   r0  = (int)r0f;
    float fr  = sr - r0f;
    bool rv0 = (r0 >= 0);
    bool rv1 = (r0 < HP - 1);
    float wr0 = 1.0f - fr;

    const uint2* pbase = g_pooled + ((size_t)b * HP * WP) * CV4 + c4;
    const uint2* rowA  = pbase + (size_t)(rv0 ? r0     : 0) * WP * CV4;
    const uint2* rowB  = pbase + (size_t)(rv1 ? r0 + 1 : 0) * WP * CV4;

    const float4 z = make_float4(0.f, 0.f, 0.f, 0.f);

    pdl_wait();      // pooled writes visible past this point

    float4 T[4];
    #pragma unroll
    for (int i = 0; i < 4; ++i) {
        int col = k0 - 1 + i;
        bool cv = (unsigned)col < (unsigned)WP;
        float4 a  = (rv0 && cv) ? unpack_h4(__ldg(rowA + (size_t)col * CV4)) : z;
        float4 bb = (rv1 && cv) ? unpack_h4(__ldg(rowB + (size_t)col * CV4)) : z;
        T[i] = blend2(a, wr0, bb, fr);
    }

    float4* op = out4 + (((size_t)b * HIN + y) * WIN + k0 * 4) * CV4 + c4;

    if (kk >= 1 && kk <= 30) {
        op[0 * CV4] = blend2(T[0], 0.375f, T[1], 0.625f);
        op[1 * CV4] = blend2(T[0], 0.125f, T[1], 0.875f);
        op[2 * CV4] = blend2(T[1], 0.875f, T[2], 0.125f);
        op[3 * CV4] = blend2(T[1], 0.625f, T[2], 0.375f);
        op[4 * CV4] = blend2(T[1], 0.375f, T[2], 0.625f);
        op[5 * CV4] = blend2(T[1], 0.125f, T[2], 0.875f);
        op[6 * CV4] = blend2(T[2], 0.875f, T[3], 0.125f);
        op[7 * CV4] = blend2(T[2], 0.625f, T[3], 0.375f);
    } else {
        int x0 = k0 * 4;
        #pragma unroll
        for (int m = 0; m < 8; ++m) {
            float sc  = d2s((float)(x0 + m));
            float c0f = floorf(sc);
            float fc  = sc - c0f;
            int idx = (int)c0f - (k0 - 1);   // 0..2
            float4 lo = (idx == 0) ? T[0] : ((idx == 1) ? T[1] : T[2]);
            float4 hi = (idx == 0) ? T[1] : ((idx == 1) ? T[2] : T[3]);
            op[m * CV4] = blend2(lo, 1.0f - fc, hi, fc);
        }
    }
}

extern "C" void kernel_launch(void* const* d_in, const int* in_sizes, int n_in,
                              void* d_out, int out_size) {
    const float4* in4 = (const float4*)d_in[0];
    float4* out4 = (float4*)d_out;

    // K1: normal launch. 16384 warps = 2048 CTAs x 256 threads.
    pool_kernel<<<2048, 256>>>(in4);

    // K2: programmatic dependent launch — overlaps into K1's tail
    cudaLaunchAttribute attrs[1];
    attrs[0].id = cudaLaunchAttributeProgrammaticStreamSerialization;
    attrs[0].val.programmaticStreamSerializationAllowed = 1;

    cudaLaunchConfig_t cfg = {};
    cfg.gridDim  = dim3((B * HIN * 32 * CV4) / 256);   // 4096 CTAs
    cfg.blockDim = dim3(256);
    cfg.attrs = attrs;
    cfg.numAttrs = 1;
    cudaLaunchKernelEx(&cfg, up_kernel, out4);
}